// round 14
// baseline (speedup 1.0000x reference)
#include <cuda_runtime.h>
#include <cuda_bf16.h>
#include <cuda_fp16.h>
#include <cstdint>

// ---------------- problem-size scratch (static __device__, no allocs) --------
#define N_MAX 100000
#define N_PAD (N_MAX + 128)
#define E_MAX 1600000

__device__ unsigned g_bufA16[(size_t)N_MAX * 64];  // fp16x2 GEMM out (128 cols)
__device__ unsigned g_bufC16[(size_t)N_MAX * 32];  // fp16x2 GEMM out (64 cols)
__device__ unsigned g_Xh[(size_t)N_PAD * 64];      // bf16x2 hi pairs (padded)
__device__ unsigned g_Xl[(size_t)N_PAD * 64];
__device__ unsigned g_Hh[(size_t)N_PAD * 64];
__device__ unsigned g_Hl[(size_t)N_PAD * 64];
__device__ float g_dinv[N_MAX];
__device__ int   g_cnt[N_MAX];
__device__ int   g_off[N_MAX + 1];
__device__ int   g_cur[N_MAX];
__device__ int   g_srcs[E_MAX];
__device__ float g_wn[E_MAX];
__device__ int   g_bsum[256];
__device__ int   g_bexc[256];
__device__ int   g_is64;

// W^T as bf16 hi/lo pairs: layout [n][kpair], i.e. n*64 + kp.
__device__ unsigned g_Bh0[128 * 64];
__device__ unsigned g_Bl0[128 * 64];
__device__ unsigned g_Bh1[128 * 64];
__device__ unsigned g_Bl1[128 * 64];
__device__ unsigned g_Bh2[64 * 64];
__device__ unsigned g_Bl2[64 * 64];

// ---------------- misc helpers -----------------------------------------------
__device__ __forceinline__ int edge_at(const void* p, long long idx) {
    if (g_is64) return (int)((const long long*)p)[idx];
    return ((const int*)p)[idx];
}

__device__ __forceinline__ uint32_t smem_u32(const void* p) {
    uint32_t a;
    asm("{ .reg .u64 t; cvta.to.shared.u64 t, %1; cvt.u32.u64 %0, t; }"
        : "=r"(a) : "l"(p));
    return a;
}

__device__ __forceinline__ void split2(float x, float y, unsigned& hi,
                                       unsigned& lo) {
    __nv_bfloat16 h0 = __float2bfloat16_rn(x);
    __nv_bfloat16 h1 = __float2bfloat16_rn(y);
    __nv_bfloat16 l0 = __float2bfloat16_rn(x - __bfloat162float(h0));
    __nv_bfloat16 l1 = __float2bfloat16_rn(y - __bfloat162float(h1));
    __nv_bfloat162 hp = __nv_bfloat162(h0, h1);
    __nv_bfloat162 lp = __nv_bfloat162(l0, l1);
    hi = *(unsigned*)&hp;
    lo = *(unsigned*)&lp;
}

// accumulate 8 fp16 lanes (one uint4) scaled by w into acc[8]
__device__ __forceinline__ void acc8(float* acc, const uint4& h, float w) {
    float2 a0 = __half22float2(*(__half2*)&h.x);
    float2 a1 = __half22float2(*(__half2*)&h.y);
    float2 a2 = __half22float2(*(__half2*)&h.z);
    float2 a3 = __half22float2(*(__half2*)&h.w);
    acc[0] += w * a0.x; acc[1] += w * a0.y;
    acc[2] += w * a1.x; acc[3] += w * a1.y;
    acc[4] += w * a2.x; acc[5] += w * a2.y;
    acc[6] += w * a3.x; acc[7] += w * a3.y;
}

// ---------------- fused prep: detect + cnt-zero + xsplit + all W preps -------
__global__ void prep_k(const float2* __restrict__ X,
                       unsigned* __restrict__ Xh, unsigned* __restrict__ Xl,
                       const float* __restrict__ W0,
                       const float* __restrict__ W1,
                       const float* __restrict__ W2,
                       unsigned* __restrict__ Bh0, unsigned* __restrict__ Bl0,
                       unsigned* __restrict__ Bh1, unsigned* __restrict__ Bl1,
                       unsigned* __restrict__ Bh2, unsigned* __restrict__ Bl2,
                       const unsigned int* __restrict__ ep, int E,
                       int n, int nx) {
    int gid = blockIdx.x * blockDim.x + threadIdx.x;
    if (gid < n) g_cnt[gid] = 0;
    if (blockIdx.x == 0) {  // edge dtype detection (int64 -> odd words all 0)
        __shared__ int any;
        if (threadIdx.x == 0) any = 0;
        __syncthreads();
        int lim = E < 8192 ? E : 8192;
        for (int j = threadIdx.x; j < lim; j += blockDim.x)
            if (ep[2 * j + 1] != 0u) any = 1;
        __syncthreads();
        if (threadIdx.x == 0) g_is64 = any ? 0 : 1;
    }
    if (gid < nx) {
        float2 f = X[gid];
        split2(f.x, f.y, Xh[gid], Xl[gid]);
        return;
    }
    int g2 = gid - nx;
    const float* Wg;
    unsigned *Bh, *Bl;
    int idx, N;
    if (g2 < 128 * 64) {
        Wg = W0; Bh = Bh0; Bl = Bl0; idx = g2; N = 128;
    } else if (g2 < 2 * 128 * 64) {
        Wg = W1; Bh = Bh1; Bl = Bl1; idx = g2 - 128 * 64; N = 128;
    } else if (g2 < 2 * 128 * 64 + 64 * 64) {
        Wg = W2; Bh = Bh2; Bl = Bl2; idx = g2 - 2 * 128 * 64; N = 64;
    } else {
        return;
    }
    int nn = idx >> 6;
    int kp = idx & 63;
    int k = 2 * kp;
    split2(Wg[(size_t)k * N + nn], Wg[(size_t)(k + 1) * N + nn], Bh[idx],
           Bl[idx]);
}

// ---------------- CSR build --------------------------------------------------
__global__ void count_k(const void* __restrict__ edges, int E) {
    int i = blockIdx.x * blockDim.x + threadIdx.x;
    if (i < E) {
        int tgt = edge_at(edges, (long long)E + i);
        atomicAdd(&g_cnt[tgt], 1);
    }
}

__global__ void scan_part_k(int n) {
    __shared__ int sh[1024];
    int t = threadIdx.x;
    int i = blockIdx.x * 1024 + t;
    int v = (i < n) ? g_cnt[i] : 0;
    if (i < n) g_dinv[i] = rsqrtf((float)(v + 1));
    int val = v;
    sh[t] = val;
    __syncthreads();
#pragma unroll
    for (int d = 1; d < 1024; d <<= 1) {
        int y = (t >= d) ? sh[t - d] : 0;
        __syncthreads();
        val += y;
        sh[t] = val;
        __syncthreads();
    }
    if (i < n) g_off[i] = val - v;
    if (t == 1023) g_bsum[blockIdx.x] = val;
}

__global__ void scan_bsum_k(int nb) {
    if (threadIdx.x == 0 && blockIdx.x == 0) {
        int run = 0;
        for (int i = 0; i < nb; i++) { g_bexc[i] = run; run += g_bsum[i]; }
    }
}

__global__ void scan_add_k(int n, int E) {
    int i = blockIdx.x * blockDim.x + threadIdx.x;
    if (i < n) {
        g_off[i] += g_bexc[i >> 10];
        g_cur[i] = 0;
    }
    if (i == 0) g_off[n] = E;
}

__global__ void fill_k(const void* __restrict__ edges, int E) {
    int i = blockIdx.x * blockDim.x + threadIdx.x;
    if (i < E) {
        int src = edge_at(edges, i);
        int tgt = edge_at(edges, (long long)E + i);
        int pos = g_off[tgt] + atomicAdd(&g_cur[tgt], 1);
        g_srcs[pos] = src;
        g_wn[pos] = g_dinv[src] * g_dinv[tgt];
    }
}

// ---------------- HMMA GEMM (R6 config): Y[:,cb:cb+64] = X[n,128] @ W --------
// 3-term bf16 split via mma.sync.m16n8k16, cp.async K-split pipeline (2
// chunks of 64 K), M128 x N64 tile via blockIdx.y column split, 2 CTAs/SM.
// Output stored as fp16 (half2 words) — halves the downstream gather traffic.
#define CST 36
#define OFF_A(c, t) ((c) * 2 * 128 * CST + (t) * 128 * CST)  // t: 0=hi 1=lo
#define OFF_B(c, t) (4 * 128 * CST + (c) * 2 * 64 * CST + (t) * 64 * CST)
#define GEMM_SMEM ((4 * 128 * CST + 4 * 64 * CST) * 4)  // 110592 B

__device__ __forceinline__ void mma16816(float* c, const unsigned* a,
                                         const unsigned* b) {
    asm volatile(
        "mma.sync.aligned.m16n8k16.row.col.f32.bf16.bf16.f32 "
        "{%0,%1,%2,%3}, {%4,%5,%6,%7}, {%8,%9}, {%0,%1,%2,%3};"
        : "+f"(c[0]), "+f"(c[1]), "+f"(c[2]), "+f"(c[3])
        : "r"(a[0]), "r"(a[1]), "r"(a[2]), "r"(a[3]), "r"(b[0]), "r"(b[1]));
}

#define LDSM4(r, addr) \
    asm volatile( \
        "ldmatrix.sync.aligned.m8n8.x4.shared.b16 {%0,%1,%2,%3}, [%4];" \
        : "=r"((r)[0]), "=r"((r)[1]), "=r"((r)[2]), "=r"((r)[3]) \
        : "r"(addr))

#define CP16(dst, src) \
    asm volatile("cp.async.cg.shared.global [%0], [%1], 16;" :: "r"(dst), \
                 "l"(src))
#define CP_COMMIT() asm volatile("cp.async.commit_group;" ::: "memory")
#define CP_WAIT1() asm volatile("cp.async.wait_group 1;" ::: "memory")
#define CP_WAIT0() asm volatile("cp.async.wait_group 0;" ::: "memory")

__global__ __launch_bounds__(256, 2) void mma_gemm_k(
    const unsigned* __restrict__ Xh, const unsigned* __restrict__ Xl,
    const unsigned* __restrict__ gBh, const unsigned* __restrict__ gBl,
    unsigned* __restrict__ Y16, int nrows, int NOUT) {
    extern __shared__ unsigned sm[];
    const uint32_t sb = smem_u32(sm);
    const int tid = threadIdx.x;
    const int wid = tid >> 5;
    const int l = tid & 31;
    const int row0 = blockIdx.x * 128;
    const int cb = blockIdx.y * 64;

    // async loads, one commit group per K-chunk (A rows unconditional: padded)
#pragma unroll
    for (int c = 0; c < 2; c++) {
#pragma unroll
        for (int i = tid; i < 128 * 8; i += 256) {
            int m = i >> 3, c4 = i & 7;
            const unsigned* srcH = Xh + (size_t)(row0 + m) * 64 + c * 32 + c4 * 4;
            const unsigned* srcL = Xl + (size_t)(row0 + m) * 64 + c * 32 + c4 * 4;
            CP16(sb + (OFF_A(c, 0) + m * CST + c4 * 4) * 4, srcH);
            CP16(sb + (OFF_A(c, 1) + m * CST + c4 * 4) * 4, srcL);
        }
#pragma unroll
        for (int i = tid; i < 64 * 8; i += 256) {
            int n = i >> 3, c4 = i & 7;
            const unsigned* srcH = gBh + (size_t)(cb + n) * 64 + c * 32 + c4 * 4;
            const unsigned* srcL = gBl + (size_t)(cb + n) * 64 + c * 32 + c4 * 4;
            CP16(sb + (OFF_B(c, 0) + n * CST + c4 * 4) * 4, srcH);
            CP16(sb + (OFF_B(c, 1) + n * CST + c4 * 4) * 4, srcL);
        }
        CP_COMMIT();
    }

    const int wm = wid & 3;   // rows 32*wm .. +32
    const int wn = wid >> 2;  // cols 32*wn .. +32
    const int lr = l >> 2;
    const int lq = l & 3;

    const uint32_t aoff =
        (((l & 7) + ((l >> 3) & 1) * 8 + wm * 32) * CST + (l >> 4) * 4) * 4;
    const uint32_t boff =
        ((wn * 32 + ((l >> 4) & 1) * 8 + (l & 7)) * CST + ((l >> 3) & 1) * 4) * 4;

    float acc[2][4][4];
#pragma unroll
    for (int mt = 0; mt < 2; mt++)
#pragma unroll
        for (int nt = 0; nt < 4; nt++)
#pragma unroll
            for (int p = 0; p < 4; p++) acc[mt][nt][p] = 0.f;

#pragma unroll
    for (int c = 0; c < 2; c++) {
        if (c == 0) CP_WAIT1(); else CP_WAIT0();
        __syncthreads();
#pragma unroll
        for (int term = 0; term < 3; term++) {
            const uint32_t aA = sb + OFF_A(c, term == 2 ? 1 : 0) * 4 + aoff;
            const uint32_t bB = sb + OFF_B(c, term == 1 ? 1 : 0) * 4 + boff;
#pragma unroll
            for (int ks = 0; ks < 4; ks++) {
                unsigned a[2][4], t0[4], t1[4];
                LDSM4(a[0], aA + ks * 32);
                LDSM4(a[1], aA + ks * 32 + 16 * CST * 4);
                LDSM4(t0, bB + ks * 32);
                LDSM4(t1, bB + ks * 32 + 16 * CST * 4);
                unsigned b[4][2] = {{t0[0], t0[1]}, {t0[2], t0[3]},
                                    {t1[0], t1[1]}, {t1[2], t1[3]}};
#pragma unroll
                for (int mt = 0; mt < 2; mt++)
#pragma unroll
                    for (int nt = 0; nt < 4; nt++)
                        mma16816(acc[mt][nt], a[mt], b[nt]);
            }
        }
    }

    // epilogue: fp16 output (one half2 word per 2 cols)
    const int NH = NOUT >> 1;
#pragma unroll
    for (int mt = 0; mt < 2; mt++) {
        int r = row0 + wm * 32 + mt * 16 + lr;
        int r2 = r + 8;
#pragma unroll
        for (int nt = 0; nt < 4; nt++) {
            int cc = cb + wn * 32 + nt * 8 + lq * 2;
            __half2 p0 = __floats2half2_rn(acc[mt][nt][0], acc[mt][nt][1]);
            __half2 p1 = __floats2half2_rn(acc[mt][nt][2], acc[mt][nt][3]);
            if (r < nrows) Y16[(size_t)r * NH + (cc >> 1)] = *(unsigned*)&p0;
            if (r2 < nrows) Y16[(size_t)r2 * NH + (cc >> 1)] = *(unsigned*)&p1;
        }
    }
}

// ---------------- aggregation (uint4 gathers: 8 cols/lane, 4-wide MLP) --------
// H: fp16 rows of F cols = F/4... each lane owns 8 cols = one uint4 (16B).
template <int F, bool RELU, bool SPLIT>
__global__ __launch_bounds__(256) void agg_k(const uint4* __restrict__ H,
                                             const float* __restrict__ bias,
                                             float* __restrict__ out,
                                             uint4* __restrict__ outH,
                                             uint4* __restrict__ outL,
                                             int n) {
    constexpr int LPN = F / 8;       // lanes per node (uint4 = 8 halves each)
    constexpr int NPW = 32 / LPN;
    int gt = blockIdx.x * blockDim.x + threadIdx.x;
    int warp = gt >> 5;
    int lane = gt & 31;
    int sub = lane / LPN;
    int ln = lane % LPN;
    int v = warp * NPW + sub;
    bool valid = v < n;
    if (v >= n) v = n - 1;

    float acc[8];
    {
        float4 b0 = ((const float4*)bias)[ln * 2];
        float4 b1 = ((const float4*)bias)[ln * 2 + 1];
        acc[0] = b0.x; acc[1] = b0.y; acc[2] = b0.z; acc[3] = b0.w;
        acc[4] = b1.x; acc[5] = b1.y; acc[6] = b1.z; acc[7] = b1.w;
    }
    float dv = g_dinv[v];
    float w0 = dv * dv;
    {
        uint4 hv = __ldcg(&H[(size_t)v * LPN + ln]);
        acc8(acc, hv, w0);
    }

    int s = g_off[v], eend = g_off[v + 1];
    for (int i = s; i < eend; i += LPN) {
        int j = i + ln;
        int src = 0;
        float w = 0.f;
        if (j < eend) { src = g_srcs[j]; w = g_wn[j]; }
        int cnt = eend - i;
        if (cnt > LPN) cnt = LPN;
        int t = 0;
        for (; t + 4 <= cnt; t += 4) {
            int s0 = __shfl_sync(0xffffffffu, src, t + 0, LPN);
            int s1 = __shfl_sync(0xffffffffu, src, t + 1, LPN);
            int s2 = __shfl_sync(0xffffffffu, src, t + 2, LPN);
            int s3 = __shfl_sync(0xffffffffu, src, t + 3, LPN);
            float w_0 = __shfl_sync(0xffffffffu, w, t + 0, LPN);
            float w_1 = __shfl_sync(0xffffffffu, w, t + 1, LPN);
            float w_2 = __shfl_sync(0xffffffffu, w, t + 2, LPN);
            float w_3 = __shfl_sync(0xffffffffu, w, t + 3, LPN);
            uint4 h0 = __ldcg(&H[(size_t)s0 * LPN + ln]);
            uint4 h1 = __ldcg(&H[(size_t)s1 * LPN + ln]);
            uint4 h2 = __ldcg(&H[(size_t)s2 * LPN + ln]);
            uint4 h3 = __ldcg(&H[(size_t)s3 * LPN + ln]);
            acc8(acc, h0, w_0);
            acc8(acc, h1, w_1);
            acc8(acc, h2, w_2);
            acc8(acc, h3, w_3);
        }
        for (; t < cnt; t++) {
            int st = __shfl_sync(0xffffffffu, src, t, LPN);
            float wt = __shfl_sync(0xffffffffu, w, t, LPN);
            uint4 hh = __ldcg(&H[(size_t)st * LPN + ln]);
            acc8(acc, hh, wt);
        }
    }

    if (RELU) {
#pragma unroll
        for (int p = 0; p < 8; p++) acc[p] = fmaxf(acc[p], 0.f);
    }
    if (!valid) return;
    if (SPLIT) {
        uint4 oh, ol;
        split2(acc[0], acc[1], oh.x, ol.x);
        split2(acc[2], acc[3], oh.y, ol.y);
        split2(acc[4], acc[5], oh.z, ol.z);
        split2(acc[6], acc[7], oh.w, ol.w);
        outH[(size_t)v * LPN + ln] = oh;
        outL[(size_t)v * LPN + ln] = ol;
    } else {
        float4* o = (float4*)(out + (size_t)v * F + ln * 8);
        o[0] = make_float4(acc[0], acc[1], acc[2], acc[3]);
        o[1] = make_float4(acc[4], acc[5], acc[6], acc[7]);
    }
}

// ---------------- launch ------------------------------------------------------
extern "C" void kernel_launch(void* const* d_in, const int* in_sizes, int n_in,
                              void* d_out, int out_size) {
    const float* x = (const float*)d_in[0];
    const void* edges = d_in[1];
    const float* W0 = (const float*)d_in[2];
    const float* b0 = (const float*)d_in[3];
    const float* W1 = (const float*)d_in[4];
    const float* b1 = (const float*)d_in[5];
    const float* W2 = (const float*)d_in[6];
    const float* b2 = (const float*)d_in[7];

    int n = in_sizes[0] / 128;
    int E = in_sizes[1] / 2;
    if (n > N_MAX) n = N_MAX;
    if (E > E_MAX) E = E_MAX;

    void *pA, *pC, *pXh, *pXl, *pHh, *pHl;
    cudaGetSymbolAddress(&pA, g_bufA16);
    cudaGetSymbolAddress(&pC, g_bufC16);
    cudaGetSymbolAddress(&pXh, g_Xh);
    cudaGetSymbolAddress(&pXl, g_Xl);
    cudaGetSymbolAddress(&pHh, g_Hh);
    cudaGetSymbolAddress(&pHl, g_Hl);
    unsigned* bufA16 = (unsigned*)pA;
    unsigned* bufC16 = (unsigned*)pC;
    unsigned* Xh = (unsigned*)pXh;
    unsigned* Xl = (unsigned*)pXl;
    unsigned* Hh = (unsigned*)pHh;
    unsigned* Hl = (unsigned*)pHl;

    void *ph0, *pl0, *ph1, *pl1, *ph2, *pl2;
    cudaGetSymbolAddress(&ph0, g_Bh0);
    cudaGetSymbolAddress(&pl0, g_Bl0);
    cudaGetSymbolAddress(&ph1, g_Bh1);
    cudaGetSymbolAddress(&pl1, g_Bl1);
    cudaGetSymbolAddress(&ph2, g_Bh2);
    cudaGetSymbolAddress(&pl2, g_Bl2);

    cudaFuncSetAttribute(mma_gemm_k,
                         cudaFuncAttributeMaxDynamicSharedMemorySize, GEMM_SMEM);

    int nb256 = (n + 255) / 256;
    int eb256 = (E + 255) / 256;
    int nb = (n + 1023) / 1024;
    int ntiles = (n + 127) / 128;
    dim3 g128(ntiles, 2);
    dim3 g64(ntiles, 1);

    int nx = n * 64;
    int prep_total = nx + 2 * 128 * 64 + 64 * 64;

    // launch order: prep(0), count(1), gemm1(2), scan(3..5), fill(6), aggs...
    prep_k<<<(prep_total + 255) / 256, 256>>>(
        (const float2*)x, Xh, Xl, W0, W1, W2, (unsigned*)ph0, (unsigned*)pl0,
        (unsigned*)ph1, (unsigned*)pl1, (unsigned*)ph2, (unsigned*)pl2,
        (const unsigned int*)edges, E, n, nx);
    count_k<<<eb256, 256>>>(edges, E);
    mma_gemm_k<<<g128, 256, GEMM_SMEM>>>(Xh, Xl, (const unsigned*)ph0,
                                         (const unsigned*)pl0, bufA16, n, 128);

    scan_part_k<<<nb, 1024>>>(n);
    scan_bsum_k<<<1, 32>>>(nb);
    scan_add_k<<<nb256, 256>>>(n, E);
    fill_k<<<eb256, 256>>>(edges, E);

    // layer 1 agg (fp16 uint4 gathers) -> split bf16
    agg_k<128, true, true><<<(n * 16 + 255) / 256, 256>>>(
        (const uint4*)bufA16, b0, nullptr, (uint4*)Hh, (uint4*)Hl, n);
    // layer 2
    mma_gemm_k<<<g128, 256, GEMM_SMEM>>>(Hh, Hl, (const unsigned*)ph1,
                                         (const unsigned*)pl1, bufA16, n, 128);
    agg_k<128, true, true><<<(n * 16 + 255) / 256, 256>>>(
        (const uint4*)bufA16, b1, nullptr, (uint4*)Xh, (uint4*)Xl, n);
    // layer 3
    mma_gemm_k<<<g64, 256, GEMM_SMEM>>>(Xh, Xl, (const unsigned*)ph2,
                                        (const unsigned*)pl2, bufC16, n, 64);
    agg_k<64, false, false><<<(n * 8 + 255) / 256, 256>>>(
        (const uint4*)bufC16, b2, (float*)d_out, nullptr, nullptr, n);
}

// round 15
// speedup vs baseline: 1.0247x; 1.0247x over previous
#include <cuda_runtime.h>
#include <cuda_bf16.h>
#include <cuda_fp16.h>
#include <cstdint>

// ---------------- problem-size scratch (static __device__, no allocs) --------
#define N_MAX 100000
#define N_PAD (N_MAX + 128)
#define E_MAX 1600000

__device__ unsigned g_bufA16[(size_t)N_MAX * 64];  // fp16x2 GEMM out (128 cols)
__device__ unsigned g_bufC16[(size_t)N_MAX * 32];  // fp16x2 GEMM out (64 cols)
__device__ unsigned g_Xh[(size_t)N_PAD * 64];      // bf16x2 hi pairs (padded)
__device__ unsigned g_Xl[(size_t)N_PAD * 64];
__device__ unsigned g_Hh[(size_t)N_PAD * 64];
__device__ unsigned g_Hl[(size_t)N_PAD * 64];
__device__ float g_dinv[N_MAX];
__device__ int   g_cnt[N_MAX];
__device__ int   g_off[N_MAX + 1];
__device__ int   g_rank[E_MAX];
__device__ int   g_srcs[E_MAX];
__device__ float g_wn[E_MAX];
__device__ int   g_bsum[256];
__device__ int   g_bexc[256];
__device__ int   g_is64;

// W^T as bf16 hi/lo pairs: layout [n][kpair], i.e. n*64 + kp.
__device__ unsigned g_Bh0[128 * 64];
__device__ unsigned g_Bl0[128 * 64];
__device__ unsigned g_Bh1[128 * 64];
__device__ unsigned g_Bl1[128 * 64];
__device__ unsigned g_Bh2[64 * 64];
__device__ unsigned g_Bl2[64 * 64];

// ---------------- misc helpers -----------------------------------------------
__device__ __forceinline__ int edge_at(const void* p, long long idx) {
    if (g_is64) return (int)((const long long*)p)[idx];
    return ((const int*)p)[idx];
}

__device__ __forceinline__ uint32_t smem_u32(const void* p) {
    uint32_t a;
    asm("{ .reg .u64 t; cvta.to.shared.u64 t, %1; cvt.u32.u64 %0, t; }"
        : "=r"(a) : "l"(p));
    return a;
}

__device__ __forceinline__ void split2(float x, float y, unsigned& hi,
                                       unsigned& lo) {
    __nv_bfloat16 h0 = __float2bfloat16_rn(x);
    __nv_bfloat16 h1 = __float2bfloat16_rn(y);
    __nv_bfloat16 l0 = __float2bfloat16_rn(x - __bfloat162float(h0));
    __nv_bfloat16 l1 = __float2bfloat16_rn(y - __bfloat162float(h1));
    __nv_bfloat162 hp = __nv_bfloat162(h0, h1);
    __nv_bfloat162 lp = __nv_bfloat162(l0, l1);
    hi = *(unsigned*)&hp;
    lo = *(unsigned*)&lp;
}

// ---------------- fused prep: detect + cnt-zero + xsplit + all W preps -------
__global__ void prep_k(const float2* __restrict__ X,
                       unsigned* __restrict__ Xh, unsigned* __restrict__ Xl,
                       const float* __restrict__ W0,
                       const float* __restrict__ W1,
                       const float* __restrict__ W2,
                       unsigned* __restrict__ Bh0, unsigned* __restrict__ Bl0,
                       unsigned* __restrict__ Bh1, unsigned* __restrict__ Bl1,
                       unsigned* __restrict__ Bh2, unsigned* __restrict__ Bl2,
                       const unsigned int* __restrict__ ep, int E,
                       int n, int nx) {
    int gid = blockIdx.x * blockDim.x + threadIdx.x;
    if (gid < n) g_cnt[gid] = 0;
    if (blockIdx.x == 0) {  // edge dtype detection (int64 -> odd words all 0)
        __shared__ int any;
        if (threadIdx.x == 0) any = 0;
        __syncthreads();
        int lim = E < 8192 ? E : 8192;
        for (int j = threadIdx.x; j < lim; j += blockDim.x)
            if (ep[2 * j + 1] != 0u) any = 1;
        __syncthreads();
        if (threadIdx.x == 0) g_is64 = any ? 0 : 1;
    }
    if (gid < nx) {
        float2 f = X[gid];
        split2(f.x, f.y, Xh[gid], Xl[gid]);
        return;
    }
    int g2 = gid - nx;
    const float* Wg;
    unsigned *Bh, *Bl;
    int idx, N;
    if (g2 < 128 * 64) {
        Wg = W0; Bh = Bh0; Bl = Bl0; idx = g2; N = 128;
    } else if (g2 < 2 * 128 * 64) {
        Wg = W1; Bh = Bh1; Bl = Bl1; idx = g2 - 128 * 64; N = 128;
    } else if (g2 < 2 * 128 * 64 + 64 * 64) {
        Wg = W2; Bh = Bh2; Bl = Bl2; idx = g2 - 2 * 128 * 64; N = 64;
    } else {
        return;
    }
    int nn = idx >> 6;
    int kp = idx & 63;
    int k = 2 * kp;
    split2(Wg[(size_t)k * N + nn], Wg[(size_t)(k + 1) * N + nn], Bh[idx],
           Bl[idx]);
}

// ---------------- CSR build --------------------------------------------------
// count also records each edge's within-bucket rank -> fill needs no atomics
__global__ void count_k(const void* __restrict__ edges, int E) {
    int i = blockIdx.x * blockDim.x + threadIdx.x;
    if (i < E) {
        int tgt = edge_at(edges, (long long)E + i);
        g_rank[i] = atomicAdd(&g_cnt[tgt], 1);
    }
}

__global__ void scan_part_k(int n) {
    __shared__ int sh[1024];
    int t = threadIdx.x;
    int i = blockIdx.x * 1024 + t;
    int v = (i < n) ? g_cnt[i] : 0;
    if (i < n) g_dinv[i] = rsqrtf((float)(v + 1));
    int val = v;
    sh[t] = val;
    __syncthreads();
#pragma unroll
    for (int d = 1; d < 1024; d <<= 1) {
        int y = (t >= d) ? sh[t - d] : 0;
        __syncthreads();
        val += y;
        sh[t] = val;
        __syncthreads();
    }
    if (i < n) g_off[i] = val - v;
    if (t == 1023) g_bsum[blockIdx.x] = val;
}

__global__ void scan_bsum_k(int nb) {
    if (threadIdx.x == 0 && blockIdx.x == 0) {
        int run = 0;
        for (int i = 0; i < nb; i++) { g_bexc[i] = run; run += g_bsum[i]; }
    }
}

__global__ void scan_add_k(int n, int E) {
    int i = blockIdx.x * blockDim.x + threadIdx.x;
    if (i < n) g_off[i] += g_bexc[i >> 10];
    if (i == 0) g_off[n] = E;
}

__global__ void fill_k(const void* __restrict__ edges, int E) {
    int i = blockIdx.x * blockDim.x + threadIdx.x;
    if (i < E) {
        int src = edge_at(edges, i);
        int tgt = edge_at(edges, (long long)E + i);
        int pos = g_off[tgt] + g_rank[i];
        g_srcs[pos] = src;
        g_wn[pos] = g_dinv[src] * g_dinv[tgt];
    }
}

// ---------------- HMMA GEMM (R6 config): Y[:,cb:cb+64] = X[n,128] @ W --------
// 3-term bf16 split via mma.sync.m16n8k16, cp.async K-split pipeline (2
// chunks of 64 K), M128 x N64 tile via blockIdx.y column split, 2 CTAs/SM.
// Output stored as fp16 (half2 words) — halves the downstream gather traffic.
#define CST 36
#define OFF_A(c, t) ((c) * 2 * 128 * CST + (t) * 128 * CST)  // t: 0=hi 1=lo
#define OFF_B(c, t) (4 * 128 * CST + (c) * 2 * 64 * CST + (t) * 64 * CST)
#define GEMM_SMEM ((4 * 128 * CST + 4 * 64 * CST) * 4)  // 110592 B

__device__ __forceinline__ void mma16816(float* c, const unsigned* a,
                                         const unsigned* b) {
    asm volatile(
        "mma.sync.aligned.m16n8k16.row.col.f32.bf16.bf16.f32 "
        "{%0,%1,%2,%3}, {%4,%5,%6,%7}, {%8,%9}, {%0,%1,%2,%3};"
        : "+f"(c[0]), "+f"(c[1]), "+f"(c[2]), "+f"(c[3])
        : "r"(a[0]), "r"(a[1]), "r"(a[2]), "r"(a[3]), "r"(b[0]), "r"(b[1]));
}

#define LDSM4(r, addr) \
    asm volatile( \
        "ldmatrix.sync.aligned.m8n8.x4.shared.b16 {%0,%1,%2,%3}, [%4];" \
        : "=r"((r)[0]), "=r"((r)[1]), "=r"((r)[2]), "=r"((r)[3]) \
        : "r"(addr))

#define CP16(dst, src) \
    asm volatile("cp.async.cg.shared.global [%0], [%1], 16;" :: "r"(dst), \
                 "l"(src))
#define CP_COMMIT() asm volatile("cp.async.commit_group;" ::: "memory")
#define CP_WAIT1() asm volatile("cp.async.wait_group 1;" ::: "memory")
#define CP_WAIT0() asm volatile("cp.async.wait_group 0;" ::: "memory")

__global__ __launch_bounds__(256, 2) void mma_gemm_k(
    const unsigned* __restrict__ Xh, const unsigned* __restrict__ Xl,
    const unsigned* __restrict__ gBh, const unsigned* __restrict__ gBl,
    unsigned* __restrict__ Y16, int nrows, int NOUT) {
    extern __shared__ unsigned sm[];
    const uint32_t sb = smem_u32(sm);
    const int tid = threadIdx.x;
    const int wid = tid >> 5;
    const int l = tid & 31;
    const int row0 = blockIdx.x * 128;
    const int cb = blockIdx.y * 64;

    // async loads, one commit group per K-chunk (A rows unconditional: padded)
#pragma unroll
    for (int c = 0; c < 2; c++) {
#pragma unroll
        for (int i = tid; i < 128 * 8; i += 256) {
            int m = i >> 3, c4 = i & 7;
            const unsigned* srcH = Xh + (size_t)(row0 + m) * 64 + c * 32 + c4 * 4;
            const unsigned* srcL = Xl + (size_t)(row0 + m) * 64 + c * 32 + c4 * 4;
            CP16(sb + (OFF_A(c, 0) + m * CST + c4 * 4) * 4, srcH);
            CP16(sb + (OFF_A(c, 1) + m * CST + c4 * 4) * 4, srcL);
        }
#pragma unroll
        for (int i = tid; i < 64 * 8; i += 256) {
            int n = i >> 3, c4 = i & 7;
            const unsigned* srcH = gBh + (size_t)(cb + n) * 64 + c * 32 + c4 * 4;
            const unsigned* srcL = gBl + (size_t)(cb + n) * 64 + c * 32 + c4 * 4;
            CP16(sb + (OFF_B(c, 0) + n * CST + c4 * 4) * 4, srcH);
            CP16(sb + (OFF_B(c, 1) + n * CST + c4 * 4) * 4, srcL);
        }
        CP_COMMIT();
    }

    const int wm = wid & 3;   // rows 32*wm .. +32
    const int wn = wid >> 2;  // cols 32*wn .. +32
    const int lr = l >> 2;
    const int lq = l & 3;

    const uint32_t aoff =
        (((l & 7) + ((l >> 3) & 1) * 8 + wm * 32) * CST + (l >> 4) * 4) * 4;
    const uint32_t boff =
        ((wn * 32 + ((l >> 4) & 1) * 8 + (l & 7)) * CST + ((l >> 3) & 1) * 4) * 4;

    float acc[2][4][4];
#pragma unroll
    for (int mt = 0; mt < 2; mt++)
#pragma unroll
        for (int nt = 0; nt < 4; nt++)
#pragma unroll
            for (int p = 0; p < 4; p++) acc[mt][nt][p] = 0.f;

#pragma unroll
    for (int c = 0; c < 2; c++) {
        if (c == 0) CP_WAIT1(); else CP_WAIT0();
        __syncthreads();
#pragma unroll
        for (int term = 0; term < 3; term++) {
            const uint32_t aA = sb + OFF_A(c, term == 2 ? 1 : 0) * 4 + aoff;
            const uint32_t bB = sb + OFF_B(c, term == 1 ? 1 : 0) * 4 + boff;
#pragma unroll
            for (int ks = 0; ks < 4; ks++) {
                unsigned a[2][4], t0[4], t1[4];
                LDSM4(a[0], aA + ks * 32);
                LDSM4(a[1], aA + ks * 32 + 16 * CST * 4);
                LDSM4(t0, bB + ks * 32);
                LDSM4(t1, bB + ks * 32 + 16 * CST * 4);
                unsigned b[4][2] = {{t0[0], t0[1]}, {t0[2], t0[3]},
                                    {t1[0], t1[1]}, {t1[2], t1[3]}};
#pragma unroll
                for (int mt = 0; mt < 2; mt++)
#pragma unroll
                    for (int nt = 0; nt < 4; nt++)
                        mma16816(acc[mt][nt], a[mt], b[nt]);
            }
        }
    }

    // epilogue: fp16 output (one half2 word per 2 cols)
    const int NH = NOUT >> 1;
#pragma unroll
    for (int mt = 0; mt < 2; mt++) {
        int r = row0 + wm * 32 + mt * 16 + lr;
        int r2 = r + 8;
#pragma unroll
        for (int nt = 0; nt < 4; nt++) {
            int cc = cb + wn * 32 + nt * 8 + lq * 2;
            __half2 p0 = __floats2half2_rn(acc[mt][nt][0], acc[mt][nt][1]);
            __half2 p1 = __floats2half2_rn(acc[mt][nt][2], acc[mt][nt][3]);
            if (r < nrows) Y16[(size_t)r * NH + (cc >> 1)] = *(unsigned*)&p0;
            if (r2 < nrows) Y16[(size_t)r2 * NH + (cc >> 1)] = *(unsigned*)&p1;
        }
    }
}

// ---------------- aggregation (R13: 4-wide, uint2 fp16 gathers via ldcg) ------
// H: fp16 rows of F cols = F/2 half2 words. Each lane owns 4 cols (one uint2).
template <int F, bool RELU, bool SPLIT>
__global__ __launch_bounds__(256) void agg_k(const uint2* __restrict__ H,
                                             const float* __restrict__ bias,
                                             float* __restrict__ out,
                                             unsigned* __restrict__ outH,
                                             unsigned* __restrict__ outL,
                                             int n) {
    constexpr int LPN = F / 4;       // lanes per node (uint2 = 4 halves each)
    constexpr int NPW = 32 / LPN;
    int gt = blockIdx.x * blockDim.x + threadIdx.x;
    int warp = gt >> 5;
    int lane = gt & 31;
    int sub = lane / LPN;
    int ln = lane % LPN;
    int v = warp * NPW + sub;
    bool valid = v < n;
    if (v >= n) v = n - 1;

    float4 acc = ((const float4*)bias)[ln];
    float dv = g_dinv[v];
    float w0 = dv * dv;
    {
        uint2 hv = __ldcg(&H[(size_t)v * LPN + ln]);
        float2 a0 = __half22float2(*(__half2*)&hv.x);
        float2 a1 = __half22float2(*(__half2*)&hv.y);
        acc.x += w0 * a0.x; acc.y += w0 * a0.y;
        acc.z += w0 * a1.x; acc.w += w0 * a1.y;
    }

    int s = g_off[v], eend = g_off[v + 1];
    for (int i = s; i < eend; i += LPN) {
        int j = i + ln;
        int src = 0;
        float w = 0.f;
        if (j < eend) { src = g_srcs[j]; w = g_wn[j]; }
        int cnt = eend - i;
        if (cnt > LPN) cnt = LPN;
        int t = 0;
        for (; t + 4 <= cnt; t += 4) {
            int s0 = __shfl_sync(0xffffffffu, src, t + 0, LPN);
            int s1 = __shfl_sync(0xffffffffu, src, t + 1, LPN);
            int s2 = __shfl_sync(0xffffffffu, src, t + 2, LPN);
            int s3 = __shfl_sync(0xffffffffu, src, t + 3, LPN);
            float w_0 = __shfl_sync(0xffffffffu, w, t + 0, LPN);
            float w_1 = __shfl_sync(0xffffffffu, w, t + 1, LPN);
            float w_2 = __shfl_sync(0xffffffffu, w, t + 2, LPN);
            float w_3 = __shfl_sync(0xffffffffu, w, t + 3, LPN);
            uint2 h0 = __ldcg(&H[(size_t)s0 * LPN + ln]);
            uint2 h1 = __ldcg(&H[(size_t)s1 * LPN + ln]);
            uint2 h2 = __ldcg(&H[(size_t)s2 * LPN + ln]);
            uint2 h3 = __ldcg(&H[(size_t)s3 * LPN + ln]);
            {
                float2 a0 = __half22float2(*(__half2*)&h0.x);
                float2 a1 = __half22float2(*(__half2*)&h0.y);
                acc.x += w_0 * a0.x; acc.y += w_0 * a0.y;
                acc.z += w_0 * a1.x; acc.w += w_0 * a1.y;
            }
            {
                float2 a0 = __half22float2(*(__half2*)&h1.x);
                float2 a1 = __half22float2(*(__half2*)&h1.y);
                acc.x += w_1 * a0.x; acc.y += w_1 * a0.y;
                acc.z += w_1 * a1.x; acc.w += w_1 * a1.y;
            }
            {
                float2 a0 = __half22float2(*(__half2*)&h2.x);
                float2 a1 = __half22float2(*(__half2*)&h2.y);
                acc.x += w_2 * a0.x; acc.y += w_2 * a0.y;
                acc.z += w_2 * a1.x; acc.w += w_2 * a1.y;
            }
            {
                float2 a0 = __half22float2(*(__half2*)&h3.x);
                float2 a1 = __half22float2(*(__half2*)&h3.y);
                acc.x += w_3 * a0.x; acc.y += w_3 * a0.y;
                acc.z += w_3 * a1.x; acc.w += w_3 * a1.y;
            }
        }
        for (; t < cnt; t++) {
            int st = __shfl_sync(0xffffffffu, src, t, LPN);
            float wt = __shfl_sync(0xffffffffu, w, t, LPN);
            uint2 hh = __ldcg(&H[(size_t)st * LPN + ln]);
            float2 a0 = __half22float2(*(__half2*)&hh.x);
            float2 a1 = __half22float2(*(__half2*)&hh.y);
            acc.x += wt * a0.x; acc.y += wt * a0.y;
            acc.z += wt * a1.x; acc.w += wt * a1.y;
        }
    }

    if (RELU) {
        acc.x = fmaxf(acc.x, 0.f); acc.y = fmaxf(acc.y, 0.f);
        acc.z = fmaxf(acc.z, 0.f); acc.w = fmaxf(acc.w, 0.f);
    }
    if (!valid) return;
    if (SPLIT) {
        unsigned h0, l0, h1, l1;
        split2(acc.x, acc.y, h0, l0);
        split2(acc.z, acc.w, h1, l1);
        ((uint2*)outH)[(size_t)v * (F / 4) + ln] = make_uint2(h0, h1);
        ((uint2*)outL)[(size_t)v * (F / 4) + ln] = make_uint2(l0, l1);
    } else {
        ((float4*)out)[(size_t)v * (F / 4) + ln] = acc;
    }
}

// ---------------- launch ------------------------------------------------------
extern "C" void kernel_launch(void* const* d_in, const int* in_sizes, int n_in,
                              void* d_out, int out_size) {
    const float* x = (const float*)d_in[0];
    const void* edges = d_in[1];
    const float* W0 = (const float*)d_in[2];
    const float* b0 = (const float*)d_in[3];
    const float* W1 = (const float*)d_in[4];
    const float* b1 = (const float*)d_in[5];
    const float* W2 = (const float*)d_in[6];
    const float* b2 = (const float*)d_in[7];

    int n = in_sizes[0] / 128;
    int E = in_sizes[1] / 2;
    if (n > N_MAX) n = N_MAX;
    if (E > E_MAX) E = E_MAX;

    void *pA, *pC, *pXh, *pXl, *pHh, *pHl;
    cudaGetSymbolAddress(&pA, g_bufA16);
    cudaGetSymbolAddress(&pC, g_bufC16);
    cudaGetSymbolAddress(&pXh, g_Xh);
    cudaGetSymbolAddress(&pXl, g_Xl);
    cudaGetSymbolAddress(&pHh, g_Hh);
    cudaGetSymbolAddress(&pHl, g_Hl);
    unsigned* bufA16 = (unsigned*)pA;
    unsigned* bufC16 = (unsigned*)pC;
    unsigned* Xh = (unsigned*)pXh;
    unsigned* Xl = (unsigned*)pXl;
    unsigned* Hh = (unsigned*)pHh;
    unsigned* Hl = (unsigned*)pHl;

    void *ph0, *pl0, *ph1, *pl1, *ph2, *pl2;
    cudaGetSymbolAddress(&ph0, g_Bh0);
    cudaGetSymbolAddress(&pl0, g_Bl0);
    cudaGetSymbolAddress(&ph1, g_Bh1);
    cudaGetSymbolAddress(&pl1, g_Bl1);
    cudaGetSymbolAddress(&ph2, g_Bh2);
    cudaGetSymbolAddress(&pl2, g_Bl2);

    cudaFuncSetAttribute(mma_gemm_k,
                         cudaFuncAttributeMaxDynamicSharedMemorySize, GEMM_SMEM);

    int nb256 = (n + 255) / 256;
    int eb256 = (E + 255) / 256;
    int nb = (n + 1023) / 1024;
    int ntiles = (n + 127) / 128;
    dim3 g128(ntiles, 2);
    dim3 g64(ntiles, 1);

    int nx = n * 64;
    int prep_total = nx + 2 * 128 * 64 + 64 * 64;

    // launch order: prep(0), count(1), gemm1(2), scan(3..5), fill(6), aggs...
    prep_k<<<(prep_total + 255) / 256, 256>>>(
        (const float2*)x, Xh, Xl, W0, W1, W2, (unsigned*)ph0, (unsigned*)pl0,
        (unsigned*)ph1, (unsigned*)pl1, (unsigned*)ph2, (unsigned*)pl2,
        (const unsigned int*)edges, E, n, nx);
    count_k<<<eb256, 256>>>(edges, E);
    mma_gemm_k<<<g128, 256, GEMM_SMEM>>>(Xh, Xl, (const unsigned*)ph0,
                                         (const unsigned*)pl0, bufA16, n, 128);

    scan_part_k<<<nb, 1024>>>(n);
    scan_bsum_k<<<1, 32>>>(nb);
    scan_add_k<<<nb256, 256>>>(n, E);
    fill_k<<<eb256, 256>>>(edges, E);

    // layer 1 agg (fp16 gathers) -> split bf16
    agg_k<128, true, true><<<(n * 32 + 255) / 256, 256>>>(
        (const uint2*)bufA16, b0, nullptr, Hh, Hl, n);
    // layer 2
    mma_gemm_k<<<g128, 256, GEMM_SMEM>>>(Hh, Hl, (const unsigned*)ph1,
                                         (const unsigned*)pl1, bufA16, n, 128);
    agg_k<128, true, true><<<(n * 32 + 255) / 256, 256>>>(
        (const uint2*)bufA16, b1, nullptr, Xh, Xl, n);
    // layer 3
    mma_gemm_k<<<g64, 256, GEMM_SMEM>>>(Xh, Xl, (const unsigned*)ph2,
                                        (const unsigned*)pl2, bufC16, n, 64);
    agg_k<64, false, false><<<(n * 16 + 255) / 256, 256>>>(
        (const uint2*)bufC16, b2, (float*)d_out, nullptr, nullptr, n);
}

// round 16
// speedup vs baseline: 1.1540x; 1.1262x over previous
#include <cuda_runtime.h>
#include <cuda_fp16.h>
#include <cstdint>

// ---------------- problem-size scratch (static __device__, no allocs) --------
#define N_MAX 100000
#define N_PAD (N_MAX + 128)
#define E_MAX 1600000

__device__ unsigned g_bufA16[(size_t)N_MAX * 64];  // fp16x2 GEMM out (128 cols)
__device__ unsigned g_bufC16[(size_t)N_MAX * 32];  // fp16x2 GEMM out (64 cols)
__device__ unsigned g_Xf[(size_t)N_PAD * 64];      // fp16x2 activations (padded)
__device__ unsigned g_Hf[(size_t)N_PAD * 64];
__device__ float g_dinv[N_MAX];
__device__ int   g_cnt[N_MAX];
__device__ int   g_off[N_MAX + 1];
__device__ int   g_rank[E_MAX];
__device__ int   g_srcs[E_MAX];
__device__ float g_wn[E_MAX];
__device__ int   g_bsum[256];
__device__ int   g_bexc[256];
__device__ int   g_is64;

// W^T as fp16 hi/lo pairs: layout [n][kpair], i.e. n*64 + kp.
__device__ unsigned g_Wh0[128 * 64];
__device__ unsigned g_Wl0[128 * 64];
__device__ unsigned g_Wh1[128 * 64];
__device__ unsigned g_Wl1[128 * 64];
__device__ unsigned g_Wh2[64 * 64];
__device__ unsigned g_Wl2[64 * 64];

// ---------------- misc helpers -----------------------------------------------
__device__ __forceinline__ int edge_at(const void* p, long long idx) {
    if (g_is64) return (int)((const long long*)p)[idx];
    return ((const int*)p)[idx];
}

__device__ __forceinline__ uint32_t smem_u32(const void* p) {
    uint32_t a;
    asm("{ .reg .u64 t; cvta.to.shared.u64 t, %1; cvt.u32.u64 %0, t; }"
        : "=r"(a) : "l"(p));
    return a;
}

// fp16 hi/lo split of a float pair
__device__ __forceinline__ void split2h(float x, float y, unsigned& hi,
                                        unsigned& lo) {
    __half2 h = __floats2half2_rn(x, y);
    float2 hf = __half22float2(h);
    __half2 l = __floats2half2_rn(x - hf.x, y - hf.y);
    hi = *(unsigned*)&h;
    lo = *(unsigned*)&l;
}

// ---------------- fused prep: detect + cnt-zero + x->fp16 + W fp16 hi/lo -----
__global__ void prep_k(const float2* __restrict__ X,
                       unsigned* __restrict__ Xf,
                       const float* __restrict__ W0,
                       const float* __restrict__ W1,
                       const float* __restrict__ W2,
                       unsigned* __restrict__ Wh0, unsigned* __restrict__ Wl0,
                       unsigned* __restrict__ Wh1, unsigned* __restrict__ Wl1,
                       unsigned* __restrict__ Wh2, unsigned* __restrict__ Wl2,
                       const unsigned int* __restrict__ ep, int E,
                       int n, int nx) {
    int gid = blockIdx.x * blockDim.x + threadIdx.x;
    if (gid < n) g_cnt[gid] = 0;
    if (blockIdx.x == 0) {  // edge dtype detection (int64 -> odd words all 0)
        __shared__ int any;
        if (threadIdx.x == 0) any = 0;
        __syncthreads();
        int lim = E < 8192 ? E : 8192;
        for (int j = threadIdx.x; j < lim; j += blockDim.x)
            if (ep[2 * j + 1] != 0u) any = 1;
        __syncthreads();
        if (threadIdx.x == 0) g_is64 = any ? 0 : 1;
    }
    if (gid < nx) {
        float2 f = X[gid];
        __half2 h = __floats2half2_rn(f.x, f.y);
        Xf[gid] = *(unsigned*)&h;
        return;
    }
    int g2 = gid - nx;
    const float* Wg;
    unsigned *Wh, *Wl;
    int idx, N;
    if (g2 < 128 * 64) {
        Wg = W0; Wh = Wh0; Wl = Wl0; idx = g2; N = 128;
    } else if (g2 < 2 * 128 * 64) {
        Wg = W1; Wh = Wh1; Wl = Wl1; idx = g2 - 128 * 64; N = 128;
    } else if (g2 < 2 * 128 * 64 + 64 * 64) {
        Wg = W2; Wh = Wh2; Wl = Wl2; idx = g2 - 2 * 128 * 64; N = 64;
    } else {
        return;
    }
    int nn = idx >> 6;
    int kp = idx & 63;
    int k = 2 * kp;
    split2h(Wg[(size_t)k * N + nn], Wg[(size_t)(k + 1) * N + nn], Wh[idx],
            Wl[idx]);
}

// ---------------- CSR build --------------------------------------------------
__global__ void count_k(const void* __restrict__ edges, int E) {
    int i = blockIdx.x * blockDim.x + threadIdx.x;
    if (i < E) {
        int tgt = edge_at(edges, (long long)E + i);
        g_rank[i] = atomicAdd(&g_cnt[tgt], 1);
    }
}

__global__ void scan_part_k(int n) {
    __shared__ int sh[1024];
    int t = threadIdx.x;
    int i = blockIdx.x * 1024 + t;
    int v = (i < n) ? g_cnt[i] : 0;
    if (i < n) g_dinv[i] = rsqrtf((float)(v + 1));
    int val = v;
    sh[t] = val;
    __syncthreads();
#pragma unroll
    for (int d = 1; d < 1024; d <<= 1) {
        int y = (t >= d) ? sh[t - d] : 0;
        __syncthreads();
        val += y;
        sh[t] = val;
        __syncthreads();
    }
    if (i < n) g_off[i] = val - v;
    if (t == 1023) g_bsum[blockIdx.x] = val;
}

__global__ void scan_bsum_k(int nb) {
    if (threadIdx.x == 0 && blockIdx.x == 0) {
        int run = 0;
        for (int i = 0; i < nb; i++) { g_bexc[i] = run; run += g_bsum[i]; }
    }
}

__global__ void scan_add_k(int n, int E) {
    int i = blockIdx.x * blockDim.x + threadIdx.x;
    if (i < n) g_off[i] += g_bexc[i >> 10];
    if (i == 0) g_off[n] = E;
}

__global__ void fill_k(const void* __restrict__ edges, int E) {
    int i = blockIdx.x * blockDim.x + threadIdx.x;
    if (i < E) {
        int src = edge_at(edges, i);
        int tgt = edge_at(edges, (long long)E + i);
        int pos = g_off[tgt] + g_rank[i];
        g_srcs[pos] = src;
        g_wn[pos] = g_dinv[src] * g_dinv[tgt];
    }
}

// ---------------- HMMA GEMM: Y[:,cb:cb+64] = X[n,128] @ W[128,:] -------------
// fp16 A (exact stored activation) x 2-term fp16 W split:
//   D = Xf*Wh + Xf*Wl  (fp32 accumulate; W residual ~2^-21, negligible)
// cp.async K-split pipeline (2 chunks of 64 K), M128 x N64 tile, 2 CTAs/SM.
// A fragments loaded once per ks and reused across both W terms.
#define CST 36
#define OFF_A(c) ((c) * 128 * CST)
#define OFF_B(c, t) (2 * 128 * CST + ((c) * 2 + (t)) * 64 * CST)
#define GEMM_SMEM ((2 * 128 * CST + 4 * 64 * CST) * 4)  // 73728 B

__device__ __forceinline__ void mma16816(float* c, const unsigned* a,
                                         const unsigned* b) {
    asm volatile(
        "mma.sync.aligned.m16n8k16.row.col.f32.f16.f16.f32 "
        "{%0,%1,%2,%3}, {%4,%5,%6,%7}, {%8,%9}, {%0,%1,%2,%3};"
        : "+f"(c[0]), "+f"(c[1]), "+f"(c[2]), "+f"(c[3])
        : "r"(a[0]), "r"(a[1]), "r"(a[2]), "r"(a[3]), "r"(b[0]), "r"(b[1]));
}

#define LDSM4(r, addr) \
    asm volatile( \
        "ldmatrix.sync.aligned.m8n8.x4.shared.b16 {%0,%1,%2,%3}, [%4];" \
        : "=r"((r)[0]), "=r"((r)[1]), "=r"((r)[2]), "=r"((r)[3]) \
        : "r"(addr))

#define CP16(dst, src) \
    asm volatile("cp.async.cg.shared.global [%0], [%1], 16;" :: "r"(dst), \
                 "l"(src))
#define CP_COMMIT() asm volatile("cp.async.commit_group;" ::: "memory")
#define CP_WAIT1() asm volatile("cp.async.wait_group 1;" ::: "memory")
#define CP_WAIT0() asm volatile("cp.async.wait_group 0;" ::: "memory")

__global__ __launch_bounds__(256, 2) void mma_gemm_k(
    const unsigned* __restrict__ Xf,
    const unsigned* __restrict__ gWh, const unsigned* __restrict__ gWl,
    unsigned* __restrict__ Y16, int nrows, int NOUT) {
    extern __shared__ unsigned sm[];
    const uint32_t sb = smem_u32(sm);
    const int tid = threadIdx.x;
    const int wid = tid >> 5;
    const int l = tid & 31;
    const int row0 = blockIdx.x * 128;
    const int cb = blockIdx.y * 64;

    // async loads, one commit group per K-chunk (A rows unconditional: padded)
#pragma unroll
    for (int c = 0; c < 2; c++) {
#pragma unroll
        for (int i = tid; i < 128 * 8; i += 256) {
            int m = i >> 3, c4 = i & 7;
            const unsigned* srcA = Xf + (size_t)(row0 + m) * 64 + c * 32 + c4 * 4;
            CP16(sb + (OFF_A(c) + m * CST + c4 * 4) * 4, srcA);
        }
#pragma unroll
        for (int i = tid; i < 64 * 8; i += 256) {
            int n = i >> 3, c4 = i & 7;
            const unsigned* srcH = gWh + (size_t)(cb + n) * 64 + c * 32 + c4 * 4;
            const unsigned* srcL = gWl + (size_t)(cb + n) * 64 + c * 32 + c4 * 4;
            CP16(sb + (OFF_B(c, 0) + n * CST + c4 * 4) * 4, srcH);
            CP16(sb + (OFF_B(c, 1) + n * CST + c4 * 4) * 4, srcL);
        }
        CP_COMMIT();
    }

    const int wm = wid & 3;   // rows 32*wm .. +32
    const int wn = wid >> 2;  // cols 32*wn .. +32
    const int lr = l >> 2;
    const int lq = l & 3;

    const uint32_t aoff =
        (((l & 7) + ((l >> 3) & 1) * 8 + wm * 32) * CST + (l >> 4) * 4) * 4;
    const uint32_t boff =
        ((wn * 32 + ((l >> 4) & 1) * 8 + (l & 7)) * CST + ((l >> 3) & 1) * 4) * 4;

    float acc[2][4][4];
#pragma unroll
    for (int mt = 0; mt < 2; mt++)
#pragma unroll
        for (int nt = 0; nt < 4; nt++)
#pragma unroll
            for (int p = 0; p < 4; p++) acc[mt][nt][p] = 0.f;

#pragma unroll
    for (int c = 0; c < 2; c++) {
        if (c == 0) CP_WAIT1(); else CP_WAIT0();
        __syncthreads();
        const uint32_t aA = sb + OFF_A(c) * 4 + aoff;
#pragma unroll
        for (int ks = 0; ks < 4; ks++) {
            unsigned a[2][4];
            LDSM4(a[0], aA + ks * 32);
            LDSM4(a[1], aA + ks * 32 + 16 * CST * 4);
#pragma unroll
            for (int term = 0; term < 2; term++) {
                const uint32_t bB = sb + OFF_B(c, term) * 4 + boff;
                unsigned t0[4], t1[4];
                LDSM4(t0, bB + ks * 32);
                LDSM4(t1, bB + ks * 32 + 16 * CST * 4);
                unsigned b[4][2] = {{t0[0], t0[1]}, {t0[2], t0[3]},
                                    {t1[0], t1[1]}, {t1[2], t1[3]}};
#pragma unroll
                for (int mt = 0; mt < 2; mt++)
#pragma unroll
                    for (int nt = 0; nt < 4; nt++)
                        mma16816(acc[mt][nt], a[mt], b[nt]);
            }
        }
    }

    // epilogue: fp16 output (one half2 word per 2 cols)
    const int NH = NOUT >> 1;
#pragma unroll
    for (int mt = 0; mt < 2; mt++) {
        int r = row0 + wm * 32 + mt * 16 + lr;
        int r2 = r + 8;
#pragma unroll
        for (int nt = 0; nt < 4; nt++) {
            int cc = cb + wn * 32 + nt * 8 + lq * 2;
            __half2 p0 = __floats2half2_rn(acc[mt][nt][0], acc[mt][nt][1]);
            __half2 p1 = __floats2half2_rn(acc[mt][nt][2], acc[mt][nt][3]);
            if (r < nrows) Y16[(size_t)r * NH + (cc >> 1)] = *(unsigned*)&p0;
            if (r2 < nrows) Y16[(size_t)r2 * NH + (cc >> 1)] = *(unsigned*)&p1;
        }
    }
}

// ---------------- aggregation (R13 4-wide, uint2 fp16 gathers via ldcg) -------
// SPLIT=true: write fp16 activations (single array) feeding the next GEMM.
template <int F, bool RELU, bool SPLIT>
__global__ __launch_bounds__(256) void agg_k(const uint2* __restrict__ H,
                                             const float* __restrict__ bias,
                                             float* __restrict__ out,
                                             unsigned* __restrict__ outF,
                                             int n) {
    constexpr int LPN = F / 4;       // lanes per node (uint2 = 4 halves each)
    constexpr int NPW = 32 / LPN;
    int gt = blockIdx.x * blockDim.x + threadIdx.x;
    int warp = gt >> 5;
    int lane = gt & 31;
    int sub = lane / LPN;
    int ln = lane % LPN;
    int v = warp * NPW + sub;
    bool valid = v < n;
    if (v >= n) v = n - 1;

    float4 acc = ((const float4*)bias)[ln];
    float dv = g_dinv[v];
    float w0 = dv * dv;
    {
        uint2 hv = __ldcg(&H[(size_t)v * LPN + ln]);
        float2 a0 = __half22float2(*(__half2*)&hv.x);
        float2 a1 = __half22float2(*(__half2*)&hv.y);
        acc.x += w0 * a0.x; acc.y += w0 * a0.y;
        acc.z += w0 * a1.x; acc.w += w0 * a1.y;
    }

    int s = g_off[v], eend = g_off[v + 1];
    for (int i = s; i < eend; i += LPN) {
        int j = i + ln;
        int src = 0;
        float w = 0.f;
        if (j < eend) { src = g_srcs[j]; w = g_wn[j]; }
        int cnt = eend - i;
        if (cnt > LPN) cnt = LPN;
        int t = 0;
        for (; t + 4 <= cnt; t += 4) {
            int s0 = __shfl_sync(0xffffffffu, src, t + 0, LPN);
            int s1 = __shfl_sync(0xffffffffu, src, t + 1, LPN);
            int s2 = __shfl_sync(0xffffffffu, src, t + 2, LPN);
            int s3 = __shfl_sync(0xffffffffu, src, t + 3, LPN);
            float w_0 = __shfl_sync(0xffffffffu, w, t + 0, LPN);
            float w_1 = __shfl_sync(0xffffffffu, w, t + 1, LPN);
            float w_2 = __shfl_sync(0xffffffffu, w, t + 2, LPN);
            float w_3 = __shfl_sync(0xffffffffu, w, t + 3, LPN);
            uint2 h0 = __ldcg(&H[(size_t)s0 * LPN + ln]);
            uint2 h1 = __ldcg(&H[(size_t)s1 * LPN + ln]);
            uint2 h2 = __ldcg(&H[(size_t)s2 * LPN + ln]);
            uint2 h3 = __ldcg(&H[(size_t)s3 * LPN + ln]);
            {
                float2 a0 = __half22float2(*(__half2*)&h0.x);
                float2 a1 = __half22float2(*(__half2*)&h0.y);
                acc.x += w_0 * a0.x; acc.y += w_0 * a0.y;
                acc.z += w_0 * a1.x; acc.w += w_0 * a1.y;
            }
            {
                float2 a0 = __half22float2(*(__half2*)&h1.x);
                float2 a1 = __half22float2(*(__half2*)&h1.y);
                acc.x += w_1 * a0.x; acc.y += w_1 * a0.y;
                acc.z += w_1 * a1.x; acc.w += w_1 * a1.y;
            }
            {
                float2 a0 = __half22float2(*(__half2*)&h2.x);
                float2 a1 = __half22float2(*(__half2*)&h2.y);
                acc.x += w_2 * a0.x; acc.y += w_2 * a0.y;
                acc.z += w_2 * a1.x; acc.w += w_2 * a1.y;
            }
            {
                float2 a0 = __half22float2(*(__half2*)&h3.x);
                float2 a1 = __half22float2(*(__half2*)&h3.y);
                acc.x += w_3 * a0.x; acc.y += w_3 * a0.y;
                acc.z += w_3 * a1.x; acc.w += w_3 * a1.y;
            }
        }
        for (; t < cnt; t++) {
            int st = __shfl_sync(0xffffffffu, src, t, LPN);
            float wt = __shfl_sync(0xffffffffu, w, t, LPN);
            uint2 hh = __ldcg(&H[(size_t)st * LPN + ln]);
            float2 a0 = __half22float2(*(__half2*)&hh.x);
            float2 a1 = __half22float2(*(__half2*)&hh.y);
            acc.x += wt * a0.x; acc.y += wt * a0.y;
            acc.z += wt * a1.x; acc.w += wt * a1.y;
        }
    }

    if (RELU) {
        acc.x = fmaxf(acc.x, 0.f); acc.y = fmaxf(acc.y, 0.f);
        acc.z = fmaxf(acc.z, 0.f); acc.w = fmaxf(acc.w, 0.f);
    }
    if (!valid) return;
    if (SPLIT) {
        __half2 p0 = __floats2half2_rn(acc.x, acc.y);
        __half2 p1 = __floats2half2_rn(acc.z, acc.w);
        ((uint2*)outF)[(size_t)v * (F / 4) + ln] =
            make_uint2(*(unsigned*)&p0, *(unsigned*)&p1);
    } else {
        ((float4*)out)[(size_t)v * (F / 4) + ln] = acc;
    }
}

// ---------------- launch ------------------------------------------------------
extern "C" void kernel_launch(void* const* d_in, const int* in_sizes, int n_in,
                              void* d_out, int out_size) {
    const float* x = (const float*)d_in[0];
    const void* edges = d_in[1];
    const float* W0 = (const float*)d_in[2];
    const float* b0 = (const float*)d_in[3];
    const float* W1 = (const float*)d_in[4];
    const float* b1 = (const float*)d_in[5];
    const float* W2 = (const float*)d_in[6];
    const float* b2 = (const float*)d_in[7];

    int n = in_sizes[0] / 128;
    int E = in_sizes[1] / 2;
    if (n > N_MAX) n = N_MAX;
    if (E > E_MAX) E = E_MAX;

    void *pA, *pC, *pXf, *pHf;
    cudaGetSymbolAddress(&pA, g_bufA16);
    cudaGetSymbolAddress(&pC, g_bufC16);
    cudaGetSymbolAddress(&pXf, g_Xf);
    cudaGetSymbolAddress(&pHf, g_Hf);
    unsigned* bufA16 = (unsigned*)pA;
    unsigned* bufC16 = (unsigned*)pC;
    unsigned* Xf = (unsigned*)pXf;
    unsigned* Hf = (unsigned*)pHf;

    void *ph0, *pl0, *ph1, *pl1, *ph2, *pl2;
    cudaGetSymbolAddress(&ph0, g_Wh0);
    cudaGetSymbolAddress(&pl0, g_Wl0);
    cudaGetSymbolAddress(&ph1, g_Wh1);
    cudaGetSymbolAddress(&pl1, g_Wl1);
    cudaGetSymbolAddress(&ph2, g_Wh2);
    cudaGetSymbolAddress(&pl2, g_Wl2);

    cudaFuncSetAttribute(mma_gemm_k,
                         cudaFuncAttributeMaxDynamicSharedMemorySize, GEMM_SMEM);

    int nb256 = (n + 255) / 256;
    int eb256 = (E + 255) / 256;
    int nb = (n + 1023) / 1024;
    int ntiles = (n + 127) / 128;
    dim3 g128(ntiles, 2);
    dim3 g64(ntiles, 1);

    int nx = n * 64;
    int prep_total = nx + 2 * 128 * 64 + 64 * 64;

    // launch order: prep(0), count(1), gemm1(2), scan(3..5), fill(6), aggs...
    prep_k<<<(prep_total + 255) / 256, 256>>>(
        (const float2*)x, Xf, W0, W1, W2, (unsigned*)ph0, (unsigned*)pl0,
        (unsigned*)ph1, (unsigned*)pl1, (unsigned*)ph2, (unsigned*)pl2,
        (const unsigned int*)edges, E, n, nx);
    count_k<<<eb256, 256>>>(edges, E);
    mma_gemm_k<<<g128, 256, GEMM_SMEM>>>(Xf, (const unsigned*)ph0,
                                         (const unsigned*)pl0, bufA16, n, 128);

    scan_part_k<<<nb, 1024>>>(n);
    scan_bsum_k<<<1, 32>>>(nb);
    scan_add_k<<<nb256, 256>>>(n, E);
    fill_k<<<eb256, 256>>>(edges, E);

    // layer 1 agg (fp16 gathers) -> fp16 activations
    agg_k<128, true, true><<<(n * 32 + 255) / 256, 256>>>(
        (const uint2*)bufA16, b0, nullptr, Hf, n);
    // layer 2
    mma_gemm_k<<<g128, 256, GEMM_SMEM>>>(Hf, (const unsigned*)ph1,
                                         (const unsigned*)pl1, bufA16, n, 128);
    agg_k<128, true, true><<<(n * 32 + 255) / 256, 256>>>(
        (const uint2*)bufA16, b1, nullptr, Xf, n);
    // layer 3
    mma_gemm_k<<<g64, 256, GEMM_SMEM>>>(Xf, (const unsigned*)ph2,
                                        (const unsigned*)pl2, bufC16, n, 64);
    agg_k<64, false, false><<<(n * 16 + 255) / 256, 256>>>(
        (const uint2*)bufC16, b2, (float*)d_out, nullptr, n);
}

// round 17
// speedup vs baseline: 1.1721x; 1.0157x over previous
#include <cuda_runtime.h>
#include <cuda_fp16.h>
#include <cstdint>

// ---------------- problem-size scratch (static __device__, no allocs) --------
#define N_MAX 100000
#define N_PAD (N_MAX + 128)
#define E_MAX 1600000

__device__ unsigned g_bufA16[(size_t)N_MAX * 64];  // fp16x2 GEMM out (128 cols)
__device__ unsigned g_bufC16[(size_t)N_MAX * 32];  // fp16x2 GEMM out (64 cols)
__device__ unsigned g_Xf[(size_t)N_PAD * 64];      // fp16x2 activations (padded)
__device__ unsigned g_Hf[(size_t)N_PAD * 64];
__device__ float g_dinv[N_MAX];
__device__ int   g_cnt[N_MAX];
__device__ int   g_off[N_MAX + 1];
__device__ int   g_rank[E_MAX];
__device__ int   g_srcs[E_MAX];
__device__ float g_wn[E_MAX];
__device__ int   g_bsum[256];
__device__ int   g_bexc[256];
__device__ int   g_is64;

// W^T as fp16 hi/lo pairs: layout [n][kpair], i.e. n*64 + kp.
__device__ unsigned g_Wh0[128 * 64];
__device__ unsigned g_Wl0[128 * 64];
__device__ unsigned g_Wh1[128 * 64];
__device__ unsigned g_Wl1[128 * 64];
__device__ unsigned g_Wh2[64 * 64];
__device__ unsigned g_Wl2[64 * 64];

// ---------------- misc helpers -----------------------------------------------
__device__ __forceinline__ int edge_at(const void* p, long long idx) {
    if (g_is64) return (int)((const long long*)p)[idx];
    return ((const int*)p)[idx];
}

__device__ __forceinline__ uint32_t smem_u32(const void* p) {
    uint32_t a;
    asm("{ .reg .u64 t; cvta.to.shared.u64 t, %1; cvt.u32.u64 %0, t; }"
        : "=r"(a) : "l"(p));
    return a;
}

// fp16 hi/lo split of a float pair
__device__ __forceinline__ void split2h(float x, float y, unsigned& hi,
                                        unsigned& lo) {
    __half2 h = __floats2half2_rn(x, y);
    float2 hf = __half22float2(h);
    __half2 l = __floats2half2_rn(x - hf.x, y - hf.y);
    hi = *(unsigned*)&h;
    lo = *(unsigned*)&l;
}

// ---------------- CSR branch: detect + cnt-zero ------------------------------
__global__ void detect_init_k(const unsigned int* __restrict__ p, int e,
                              int n) {
    int i = blockIdx.x * blockDim.x + threadIdx.x;
    if (i < n) g_cnt[i] = 0;
    if (blockIdx.x == 0) {
        __shared__ int any;
        if (threadIdx.x == 0) any = 0;
        __syncthreads();
        int lim = e < 8192 ? e : 8192;
        for (int j = threadIdx.x; j < lim; j += blockDim.x)
            if (p[2 * j + 1] != 0u) any = 1;
        __syncthreads();
        if (threadIdx.x == 0) g_is64 = any ? 0 : 1;
    }
}

// ---------------- GEMM branch prep: x->fp16 + W fp16 hi/lo -------------------
__global__ void prep_k(const float2* __restrict__ X,
                       unsigned* __restrict__ Xf,
                       const float* __restrict__ W0,
                       const float* __restrict__ W1,
                       const float* __restrict__ W2,
                       unsigned* __restrict__ Wh0, unsigned* __restrict__ Wl0,
                       unsigned* __restrict__ Wh1, unsigned* __restrict__ Wl1,
                       unsigned* __restrict__ Wh2, unsigned* __restrict__ Wl2,
                       int nx) {
    int gid = blockIdx.x * blockDim.x + threadIdx.x;
    if (gid < nx) {
        float2 f = X[gid];
        __half2 h = __floats2half2_rn(f.x, f.y);
        Xf[gid] = *(unsigned*)&h;
        return;
    }
    int g2 = gid - nx;
    const float* Wg;
    unsigned *Wh, *Wl;
    int idx, N;
    if (g2 < 128 * 64) {
        Wg = W0; Wh = Wh0; Wl = Wl0; idx = g2; N = 128;
    } else if (g2 < 2 * 128 * 64) {
        Wg = W1; Wh = Wh1; Wl = Wl1; idx = g2 - 128 * 64; N = 128;
    } else if (g2 < 2 * 128 * 64 + 64 * 64) {
        Wg = W2; Wh = Wh2; Wl = Wl2; idx = g2 - 2 * 128 * 64; N = 64;
    } else {
        return;
    }
    int nn = idx >> 6;
    int kp = idx & 63;
    int k = 2 * kp;
    split2h(Wg[(size_t)k * N + nn], Wg[(size_t)(k + 1) * N + nn], Wh[idx],
            Wl[idx]);
}

// ---------------- CSR build --------------------------------------------------
__global__ void count_k(const void* __restrict__ edges, int E) {
    int i = blockIdx.x * blockDim.x + threadIdx.x;
    if (i < E) {
        int tgt = edge_at(edges, (long long)E + i);
        g_rank[i] = atomicAdd(&g_cnt[tgt], 1);
    }
}

__global__ void scan_part_k(int n) {
    __shared__ int sh[1024];
    int t = threadIdx.x;
    int i = blockIdx.x * 1024 + t;
    int v = (i < n) ? g_cnt[i] : 0;
    if (i < n) g_dinv[i] = rsqrtf((float)(v + 1));
    int val = v;
    sh[t] = val;
    __syncthreads();
#pragma unroll
    for (int d = 1; d < 1024; d <<= 1) {
        int y = (t >= d) ? sh[t - d] : 0;
        __syncthreads();
        val += y;
        sh[t] = val;
        __syncthreads();
    }
    if (i < n) g_off[i] = val - v;
    if (t == 1023) g_bsum[blockIdx.x] = val;
}

__global__ void scan_bsum_k(int nb) {
    if (threadIdx.x == 0 && blockIdx.x == 0) {
        int run = 0;
        for (int i = 0; i < nb; i++) { g_bexc[i] = run; run += g_bsum[i]; }
    }
}

__global__ void scan_add_k(int n, int E) {
    int i = blockIdx.x * blockDim.x + threadIdx.x;
    if (i < n) g_off[i] += g_bexc[i >> 10];
    if (i == 0) g_off[n] = E;
}

__global__ void fill_k(const void* __restrict__ edges, int E) {
    int i = blockIdx.x * blockDim.x + threadIdx.x;
    if (i < E) {
        int src = edge_at(edges, i);
        int tgt = edge_at(edges, (long long)E + i);
        int pos = g_off[tgt] + g_rank[i];
        g_srcs[pos] = src;
        g_wn[pos] = g_dinv[src] * g_dinv[tgt];
    }
}

// ---------------- HMMA GEMM: Y[:,cb:cb+64] = X[n,128] @ W[128,:] -------------
// fp16 A (exact stored activation) x 2-term fp16 W split:
//   D = Xf*Wh + Xf*Wl  (fp32 accumulate; W residual ~2^-21, negligible)
// cp.async K-split pipeline (2 chunks of 64 K), M128 x N64 tile, 2 CTAs/SM.
#define CST 36
#define OFF_A(c) ((c) * 128 * CST)
#define OFF_B(c, t) (2 * 128 * CST + ((c) * 2 + (t)) * 64 * CST)
#define GEMM_SMEM ((2 * 128 * CST + 4 * 64 * CST) * 4)  // 73728 B

__device__ __forceinline__ void mma16816(float* c, const unsigned* a,
                                         const unsigned* b) {
    asm volatile(
        "mma.sync.aligned.m16n8k16.row.col.f32.f16.f16.f32 "
        "{%0,%1,%2,%3}, {%4,%5,%6,%7}, {%8,%9}, {%0,%1,%2,%3};"
        : "+f"(c[0]), "+f"(c[1]), "+f"(c[2]), "+f"(c[3])
        : "r"(a[0]), "r"(a[1]), "r"(a[2]), "r"(a[3]), "r"(b[0]), "r"(b[1]));
}

#define LDSM4(r, addr) \
    asm volatile( \
        "ldmatrix.sync.aligned.m8n8.x4.shared.b16 {%0,%1,%2,%3}, [%4];" \
        : "=r"((r)[0]), "=r"((r)[1]), "=r"((r)[2]), "=r"((r)[3]) \
        : "r"(addr))

#define CP16(dst, src) \
    asm volatile("cp.async.cg.shared.global [%0], [%1], 16;" :: "r"(dst), \
                 "l"(src))
#define CP_COMMIT() asm volatile("cp.async.commit_group;" ::: "memory")
#define CP_WAIT1() asm volatile("cp.async.wait_group 1;" ::: "memory")
#define CP_WAIT0() asm volatile("cp.async.wait_group 0;" ::: "memory")

__global__ __launch_bounds__(256, 2) void mma_gemm_k(
    const unsigned* __restrict__ Xf,
    const unsigned* __restrict__ gWh, const unsigned* __restrict__ gWl,
    unsigned* __restrict__ Y16, int nrows, int NOUT) {
    extern __shared__ unsigned sm[];
    const uint32_t sb = smem_u32(sm);
    const int tid = threadIdx.x;
    const int wid = tid >> 5;
    const int l = tid & 31;
    const int row0 = blockIdx.x * 128;
    const int cb = blockIdx.y * 64;

#pragma unroll
    for (int c = 0; c < 2; c++) {
#pragma unroll
        for (int i = tid; i < 128 * 8; i += 256) {
            int m = i >> 3, c4 = i & 7;
            const unsigned* srcA = Xf + (size_t)(row0 + m) * 64 + c * 32 + c4 * 4;
            CP16(sb + (OFF_A(c) + m * CST + c4 * 4) * 4, srcA);
        }
#pragma unroll
        for (int i = tid; i < 64 * 8; i += 256) {
            int n = i >> 3, c4 = i & 7;
            const unsigned* srcH = gWh + (size_t)(cb + n) * 64 + c * 32 + c4 * 4;
            const unsigned* srcL = gWl + (size_t)(cb + n) * 64 + c * 32 + c4 * 4;
            CP16(sb + (OFF_B(c, 0) + n * CST + c4 * 4) * 4, srcH);
            CP16(sb + (OFF_B(c, 1) + n * CST + c4 * 4) * 4, srcL);
        }
        CP_COMMIT();
    }

    const int wm = wid & 3;   // rows 32*wm .. +32
    const int wn = wid >> 2;  // cols 32*wn .. +32
    const int lr = l >> 2;
    const int lq = l & 3;

    const uint32_t aoff =
        (((l & 7) + ((l >> 3) & 1) * 8 + wm * 32) * CST + (l >> 4) * 4) * 4;
    const uint32_t boff =
        ((wn * 32 + ((l >> 4) & 1) * 8 + (l & 7)) * CST + ((l >> 3) & 1) * 4) * 4;

    float acc[2][4][4];
#pragma unroll
    for (int mt = 0; mt < 2; mt++)
#pragma unroll
        for (int nt = 0; nt < 4; nt++)
#pragma unroll
            for (int p = 0; p < 4; p++) acc[mt][nt][p] = 0.f;

#pragma unroll
    for (int c = 0; c < 2; c++) {
        if (c == 0) CP_WAIT1(); else CP_WAIT0();
        __syncthreads();
        const uint32_t aA = sb + OFF_A(c) * 4 + aoff;
#pragma unroll
        for (int ks = 0; ks < 4; ks++) {
            unsigned a[2][4];
            LDSM4(a[0], aA + ks * 32);
            LDSM4(a[1], aA + ks * 32 + 16 * CST * 4);
#pragma unroll
            for (int term = 0; term < 2; term++) {
                const uint32_t bB = sb + OFF_B(c, term) * 4 + boff;
                unsigned t0[4], t1[4];
                LDSM4(t0, bB + ks * 32);
                LDSM4(t1, bB + ks * 32 + 16 * CST * 4);
                unsigned b[4][2] = {{t0[0], t0[1]}, {t0[2], t0[3]},
                                    {t1[0], t1[1]}, {t1[2], t1[3]}};
#pragma unroll
                for (int mt = 0; mt < 2; mt++)
#pragma unroll
                    for (int nt = 0; nt < 4; nt++)
                        mma16816(acc[mt][nt], a[mt], b[nt]);
            }
        }
    }

    // epilogue: fp16 output (one half2 word per 2 cols)
    const int NH = NOUT >> 1;
#pragma unroll
    for (int mt = 0; mt < 2; mt++) {
        int r = row0 + wm * 32 + mt * 16 + lr;
        int r2 = r + 8;
#pragma unroll
        for (int nt = 0; nt < 4; nt++) {
            int cc = cb + wn * 32 + nt * 8 + lq * 2;
            __half2 p0 = __floats2half2_rn(acc[mt][nt][0], acc[mt][nt][1]);
            __half2 p1 = __floats2half2_rn(acc[mt][nt][2], acc[mt][nt][3]);
            if (r < nrows) Y16[(size_t)r * NH + (cc >> 1)] = *(unsigned*)&p0;
            if (r2 < nrows) Y16[(size_t)r2 * NH + (cc >> 1)] = *(unsigned*)&p1;
        }
    }
}

// ---------------- aggregation (R13 4-wide, uint2 fp16 gathers via ldcg) -------
template <int F, bool RELU, bool SPLIT>
__global__ __launch_bounds__(256) void agg_k(const uint2* __restrict__ H,
                                             const float* __restrict__ bias,
                                             float* __restrict__ out,
                                             unsigned* __restrict__ outF,
                                             int n) {
    constexpr int LPN = F / 4;       // lanes per node (uint2 = 4 halves each)
    constexpr int NPW = 32 / LPN;
    int gt = blockIdx.x * blockDim.x + threadIdx.x;
    int warp = gt >> 5;
    int lane = gt & 31;
    int sub = lane / LPN;
    int ln = lane % LPN;
    int v = warp * NPW + sub;
    bool valid = v < n;
    if (v >= n) v = n - 1;

    float4 acc = ((const float4*)bias)[ln];
    float dv = g_dinv[v];
    float w0 = dv * dv;
    {
        uint2 hv = __ldcg(&H[(size_t)v * LPN + ln]);
        float2 a0 = __half22float2(*(__half2*)&hv.x);
        float2 a1 = __half22float2(*(__half2*)&hv.y);
        acc.x += w0 * a0.x; acc.y += w0 * a0.y;
        acc.z += w0 * a1.x; acc.w += w0 * a1.y;
    }

    int s = g_off[v], eend = g_off[v + 1];
    for (int i = s; i < eend; i += LPN) {
        int j = i + ln;
        int src = 0;
        float w = 0.f;
        if (j < eend) { src = g_srcs[j]; w = g_wn[j]; }
        int cnt = eend - i;
        if (cnt > LPN) cnt = LPN;
        int t = 0;
        for (; t + 4 <= cnt; t += 4) {
            int s0 = __shfl_sync(0xffffffffu, src, t + 0, LPN);
            int s1 = __shfl_sync(0xffffffffu, src, t + 1, LPN);
            int s2 = __shfl_sync(0xffffffffu, src, t + 2, LPN);
            int s3 = __shfl_sync(0xffffffffu, src, t + 3, LPN);
            float w_0 = __shfl_sync(0xffffffffu, w, t + 0, LPN);
            float w_1 = __shfl_sync(0xffffffffu, w, t + 1, LPN);
            float w_2 = __shfl_sync(0xffffffffu, w, t + 2, LPN);
            float w_3 = __shfl_sync(0xffffffffu, w, t + 3, LPN);
            uint2 h0 = __ldcg(&H[(size_t)s0 * LPN + ln]);
            uint2 h1 = __ldcg(&H[(size_t)s1 * LPN + ln]);
            uint2 h2 = __ldcg(&H[(size_t)s2 * LPN + ln]);
            uint2 h3 = __ldcg(&H[(size_t)s3 * LPN + ln]);
            {
                float2 a0 = __half22float2(*(__half2*)&h0.x);
                float2 a1 = __half22float2(*(__half2*)&h0.y);
                acc.x += w_0 * a0.x; acc.y += w_0 * a0.y;
                acc.z += w_0 * a1.x; acc.w += w_0 * a1.y;
            }
            {
                float2 a0 = __half22float2(*(__half2*)&h1.x);
                float2 a1 = __half22float2(*(__half2*)&h1.y);
                acc.x += w_1 * a0.x; acc.y += w_1 * a0.y;
                acc.z += w_1 * a1.x; acc.w += w_1 * a1.y;
            }
            {
                float2 a0 = __half22float2(*(__half2*)&h2.x);
                float2 a1 = __half22float2(*(__half2*)&h2.y);
                acc.x += w_2 * a0.x; acc.y += w_2 * a0.y;
                acc.z += w_2 * a1.x; acc.w += w_2 * a1.y;
            }
            {
                float2 a0 = __half22float2(*(__half2*)&h3.x);
                float2 a1 = __half22float2(*(__half2*)&h3.y);
                acc.x += w_3 * a0.x; acc.y += w_3 * a0.y;
                acc.z += w_3 * a1.x; acc.w += w_3 * a1.y;
            }
        }
        for (; t < cnt; t++) {
            int st = __shfl_sync(0xffffffffu, src, t, LPN);
            float wt = __shfl_sync(0xffffffffu, w, t, LPN);
            uint2 hh = __ldcg(&H[(size_t)st * LPN + ln]);
            float2 a0 = __half22float2(*(__half2*)&hh.x);
            float2 a1 = __half22float2(*(__half2*)&hh.y);
            acc.x += wt * a0.x; acc.y += wt * a0.y;
            acc.z += wt * a1.x; acc.w += wt * a1.y;
        }
    }

    if (RELU) {
        acc.x = fmaxf(acc.x, 0.f); acc.y = fmaxf(acc.y, 0.f);
        acc.z = fmaxf(acc.z, 0.f); acc.w = fmaxf(acc.w, 0.f);
    }
    if (!valid) return;
    if (SPLIT) {
        __half2 p0 = __floats2half2_rn(acc.x, acc.y);
        __half2 p1 = __floats2half2_rn(acc.z, acc.w);
        ((uint2*)outF)[(size_t)v * (F / 4) + ln] =
            make_uint2(*(unsigned*)&p0, *(unsigned*)&p1);
    } else {
        ((float4*)out)[(size_t)v * (F / 4) + ln] = acc;
    }
}

// ---------------- launch ------------------------------------------------------
extern "C" void kernel_launch(void* const* d_in, const int* in_sizes, int n_in,
                              void* d_out, int out_size) {
    const float* x = (const float*)d_in[0];
    const void* edges = d_in[1];
    const float* W0 = (const float*)d_in[2];
    const float* b0 = (const float*)d_in[3];
    const float* W1 = (const float*)d_in[4];
    const float* b1 = (const float*)d_in[5];
    const float* W2 = (const float*)d_in[6];
    const float* b2 = (const float*)d_in[7];

    int n = in_sizes[0] / 128;
    int E = in_sizes[1] / 2;
    if (n > N_MAX) n = N_MAX;
    if (E > E_MAX) E = E_MAX;

    void *pA, *pC, *pXf, *pHf;
    cudaGetSymbolAddress(&pA, g_bufA16);
    cudaGetSymbolAddress(&pC, g_bufC16);
    cudaGetSymbolAddress(&pXf, g_Xf);
    cudaGetSymbolAddress(&pHf, g_Hf);
    unsigned* bufA16 = (unsigned*)pA;
    unsigned* bufC16 = (unsigned*)pC;
    unsigned* Xf = (unsigned*)pXf;
    unsigned* Hf = (unsigned*)pHf;

    void *ph0, *pl0, *ph1, *pl1, *ph2, *pl2;
    cudaGetSymbolAddress(&ph0, g_Wh0);
    cudaGetSymbolAddress(&pl0, g_Wl0);
    cudaGetSymbolAddress(&ph1, g_Wh1);
    cudaGetSymbolAddress(&pl1, g_Wl1);
    cudaGetSymbolAddress(&ph2, g_Wh2);
    cudaGetSymbolAddress(&pl2, g_Wl2);

    cudaFuncSetAttribute(mma_gemm_k,
                         cudaFuncAttributeMaxDynamicSharedMemorySize, GEMM_SMEM);

    // side stream + events, created once on the first (uncaptured) call
    static cudaStream_t s2 = nullptr;
    static cudaEvent_t e1 = nullptr, e2 = nullptr;
    static bool fork_ok = false;
    if (!s2) {
        fork_ok =
            (cudaStreamCreateWithFlags(&s2, cudaStreamNonBlocking) == cudaSuccess) &&
            (cudaEventCreateWithFlags(&e1, cudaEventDisableTiming) == cudaSuccess) &&
            (cudaEventCreateWithFlags(&e2, cudaEventDisableTiming) == cudaSuccess);
        if (!fork_ok) s2 = (cudaStream_t)0;
    }
    cudaStream_t sc = fork_ok ? s2 : (cudaStream_t)0;

    int nb256 = (n + 255) / 256;
    int eb256 = (E + 255) / 256;
    int nb = (n + 1023) / 1024;
    int ntiles = (n + 127) / 128;
    dim3 g128(ntiles, 2);
    dim3 g64(ntiles, 1);

    int nx = n * 64;
    int prep_total = nx + 2 * 128 * 64 + 64 * 64;

    // fork: CSR branch on sc, GEMM branch on default stream
    if (fork_ok) {
        cudaEventRecord(e1, 0);
        cudaStreamWaitEvent(sc, e1, 0);
    }

    // CSR branch (stream sc): detect+zero -> count -> scan -> fill
    detect_init_k<<<nb256, 256, 0, sc>>>((const unsigned int*)edges, E, n);
    count_k<<<eb256, 256, 0, sc>>>(edges, E);
    scan_part_k<<<nb, 1024, 0, sc>>>(n);
    scan_bsum_k<<<1, 32, 0, sc>>>(nb);
    scan_add_k<<<nb256, 256, 0, sc>>>(n, E);
    fill_k<<<eb256, 256, 0, sc>>>(edges, E);
    if (fork_ok) cudaEventRecord(e2, sc);

    // GEMM branch (default stream): prep -> gemm1
    prep_k<<<(prep_total + 255) / 256, 256>>>(
        (const float2*)x, Xf, W0, W1, W2, (unsigned*)ph0, (unsigned*)pl0,
        (unsigned*)ph1, (unsigned*)pl1, (unsigned*)ph2, (unsigned*)pl2, nx);
    mma_gemm_k<<<g128, 256, GEMM_SMEM>>>(Xf, (const unsigned*)ph0,
                                         (const unsigned*)pl0, bufA16, n, 128);

    // join: aggs need the CSR
    if (fork_ok) cudaStreamWaitEvent((cudaStream_t)0, e2, 0);

    // layer 1 agg (fp16 gathers) -> fp16 activations
    agg_k<128, true, true><<<(n * 32 + 255) / 256, 256>>>(
        (const uint2*)bufA16, b0, nullptr, Hf, n);
    // layer 2
    mma_gemm_k<<<g128, 256, GEMM_SMEM>>>(Hf, (const unsigned*)ph1,
                                         (const unsigned*)pl1, bufA16, n, 128);
    agg_k<128, true, true><<<(n * 32 + 255) / 256, 256>>>(
        (const uint2*)bufA16, b1, nullptr, Xf, n);
    // layer 3
    mma_gemm_k<<<g64, 256, GEMM_SMEM>>>(Xf, (const unsigned*)ph2,
                                        (const unsigned*)pl2, bufC16, n, 64);
    agg_k<64, false, false><<<(n * 16 + 255) / 256, 256>>>(
        (const uint2*)bufC16, b2, (float*)d_out, nullptr, n);
}